// round 8
// baseline (speedup 1.0000x reference)
#include <cuda_runtime.h>
#include <cstdint>

#define BATCH 8
#define HEADS 8
#define NSEQ  4096
#define DM    512
#define DH    64
#define RP    256
#define MTOT  (BATCH*NSEQ)

__device__ float g_xc[MTOT*DM];          // tf32(x)
__device__ float g_wc[4*DM*DM];          // tf32(wq,wk,wv,wo)
__device__ float g_Ec[HEADS*NSEQ*RP];    // tf32(E)
__device__ float g_Fc[HEADS*NSEQ*RP];    // tf32(F)
__device__ float g_Q [BATCH*HEADS*NSEQ*DH];   // raw f32
__device__ float g_K [BATCH*HEADS*NSEQ*DH];   // tf32 values
__device__ float g_V [BATCH*HEADS*NSEQ*DH];   // tf32 values
__device__ float g_KP[BATCH*HEADS*RP*DH];     // raw f32
__device__ float g_VP[BATCH*HEADS*RP*DH];     // raw f32
__device__ float g_AO[BATCH*NSEQ*DM];         // tf32 values

// ---------------- helpers ----------------
__device__ __forceinline__ float f2tf(float f) {
    unsigned u; asm("cvt.rna.tf32.f32 %0, %1;" : "=r"(u) : "f"(f));
    return __uint_as_float(u);
}
__device__ __forceinline__ float4 cvt4(float4 v) {
    return make_float4(f2tf(v.x), f2tf(v.y), f2tf(v.z), f2tf(v.w));
}
__device__ __forceinline__ void mma_tf32(float c[4], float a0, float a1, float a2, float a3,
                                         float b0, float b1) {
    asm volatile(
        "mma.sync.aligned.m16n8k8.row.col.f32.tf32.tf32.f32 "
        "{%0,%1,%2,%3},{%4,%5,%6,%7},{%8,%9},{%0,%1,%2,%3};\n"
        : "+f"(c[0]), "+f"(c[1]), "+f"(c[2]), "+f"(c[3])
        : "r"(__float_as_uint(a0)), "r"(__float_as_uint(a1)),
          "r"(__float_as_uint(a2)), "r"(__float_as_uint(a3)),
          "r"(__float_as_uint(b0)), "r"(__float_as_uint(b1)));
}
__device__ __forceinline__ uint32_t s2u(const void* p) {
    return (uint32_t)__cvta_generic_to_shared(p);
}
__device__ __forceinline__ void cpa16(uint32_t dst, const void* src) {
    asm volatile("cp.async.cg.shared.global [%0], [%1], 16;\n" :: "r"(dst), "l"(src));
}
__device__ __forceinline__ void cpcommit() {
    asm volatile("cp.async.commit_group;\n" ::: "memory");
}
template<int N> __device__ __forceinline__ void cpwait() {
    asm volatile("cp.async.wait_group %0;\n" :: "n"(N) : "memory");
}

// ---------------- marshal: elementwise tf32 convert ----------------
__global__ void cvtk(const float* __restrict__ s, float* __restrict__ d, int n) {
    int i = (blockIdx.x * 256 + threadIdx.x) * 4;
    if (i >= n) return;
    *(float4*)(d + i) = cvt4(*(const float4*)(s + i));
}

// =====================================================================
// Kernel 1: QKV.  BM=BN=128 BK=32, 3-stage cp.async.
// Inner loop: pure LDS + HMMA (operands pre-converted).
// =====================================================================
#define QA (128*36)
#define QB (32*136)
#define QSTG (QA+QB)
#define QKV_SMEM (3*QSTG*4)

__global__ __launch_bounds__(256, 2) void qkv_kernel()
{
    extern __shared__ float sm[];

    const float* w = g_wc + blockIdx.z * DM * DM;
    float* outp = (blockIdx.z == 0) ? g_Q : (blockIdx.z == 1) ? g_K : g_V;

    const int m0 = blockIdx.y * 128, n0 = blockIdx.x * 128;
    const int tid = threadIdx.x;
    const int wid = tid >> 5, lane = tid & 31, g = lane >> 2, tig = lane & 3;
    const int wm = (wid >> 1) * 32, wn = (wid & 1) * 64;

    const int arow = tid >> 3, acol = (tid & 7) * 4;
    const int brow = tid >> 5, bcol = (tid & 31) * 4;

    float acc[2][8][4] = {};

    auto load = [&](int s) {
        float* buf = sm + (s % 3) * QSTG;
        const int k0 = s * 32;
        const uint32_t ab = s2u(buf), bb = s2u(buf + QA);
        #pragma unroll
        for (int l = 0; l < 4; l++) {
            int r = l * 32 + arow;
            cpa16(ab + (r * 36 + acol) * 4, &g_xc[(m0 + r) * DM + k0 + acol]);
        }
        #pragma unroll
        for (int l = 0; l < 4; l++) {
            int r = l * 8 + brow;
            cpa16(bb + (r * 136 + bcol) * 4, &w[(k0 + r) * DM + n0 + bcol]);
        }
        cpcommit();
    };

    load(0); load(1);
    for (int s = 0; s < 16; s++) {
        if (s + 2 < 16) { load(s + 2); cpwait<2>(); }
        else if (s + 1 < 16) { cpwait<1>(); }
        else { cpwait<0>(); }
        __syncthreads();

        const float* A = sm + (s % 3) * QSTG;
        const float* B = A + QA;
        #pragma unroll
        for (int ks = 0; ks < 4; ks++) {
            int kb = ks * 8;
            float a[2][4];
            #pragma unroll
            for (int mt = 0; mt < 2; mt++) {
                int r = wm + mt * 16;
                a[mt][0] = A[(r + g)     * 36 + kb + tig];
                a[mt][1] = A[(r + g + 8) * 36 + kb + tig];
                a[mt][2] = A[(r + g)     * 36 + kb + tig + 4];
                a[mt][3] = A[(r + g + 8) * 36 + kb + tig + 4];
            }
            #pragma unroll
            for (int nt = 0; nt < 8; nt++) {
                float b0 = B[(kb + tig)     * 136 + wn + nt * 8 + g];
                float b1 = B[(kb + tig + 4) * 136 + wn + nt * 8 + g];
                #pragma unroll
                for (int mt = 0; mt < 2; mt++)
                    mma_tf32(acc[mt][nt], a[mt][0], a[mt][1], a[mt][2], a[mt][3], b0, b1);
            }
        }
        __syncthreads();
    }

    const bool cv = (blockIdx.z != 0);   // K,V stored pre-converted for proj
    #pragma unroll
    for (int mt = 0; mt < 2; mt++) {
        #pragma unroll
        for (int i = 0; i < 2; i++) {
            int m = m0 + wm + mt * 16 + g + i * 8;
            int bb2 = m >> 12, ns = m & (NSEQ - 1);
            #pragma unroll
            for (int nt = 0; nt < 8; nt++) {
                int c = n0 + wn + nt * 8 + tig * 2;
                int h = c >> 6, dh = c & 63;
                float v0 = acc[mt][nt][i * 2], v1 = acc[mt][nt][i * 2 + 1];
                if (cv) { v0 = f2tf(v0); v1 = f2tf(v1); }
                *(float2*)&outp[((bb2 * HEADS + h) * NSEQ + ns) * DH + dh] =
                    make_float2(v0, v1);
            }
        }
    }
}

// =====================================================================
// Kernel 2: low-rank proj.  BM=128(r) BN=64(d) BK=32, K=4096, 3-stage.
// =====================================================================
#define PA (32*136)
#define PB (32*72)
#define PSTG (PA+PB)
#define PRJ_SMEM (3*PSTG*4)

__global__ __launch_bounds__(256, 2) void proj_kernel()
{
    extern __shared__ float sm[];

    const int bh = blockIdx.y, h = bh & 7;
    const int r0 = blockIdx.x * 128;
    const float* P = (blockIdx.z == 0 ? g_Ec : g_Fc) + h * NSEQ * RP;
    const float* S = (blockIdx.z == 0 ? g_K : g_V) + bh * NSEQ * DH;
    float*       D = (blockIdx.z == 0 ? g_KP : g_VP) + bh * RP * DH;

    const int tid = threadIdx.x;
    const int wid = tid >> 5, lane = tid & 31, g = lane >> 2, tig = lane & 3;
    const int wm = (wid >> 1) * 32, wn = (wid & 1) * 32;

    const int arow = tid >> 5, acol = (tid & 31) * 4;
    const int brow = tid >> 4, bcol = (tid & 15) * 4;

    float acc[2][4][4] = {};

    auto load = [&](int s) {
        float* buf = sm + (s % 3) * PSTG;
        const int k0 = s * 32;
        const uint32_t ab = s2u(buf), bb = s2u(buf + PA);
        #pragma unroll
        for (int l = 0; l < 4; l++) {
            int r = l * 8 + arow;
            cpa16(ab + (r * 136 + acol) * 4, &P[(k0 + r) * RP + r0 + acol]);
        }
        #pragma unroll
        for (int l = 0; l < 2; l++) {
            int r = l * 16 + brow;
            cpa16(bb + (r * 72 + bcol) * 4, &S[(k0 + r) * DH + bcol]);
        }
        cpcommit();
    };

    const int NST = NSEQ / 32;
    load(0); load(1);
    for (int s = 0; s < NST; s++) {
        if (s + 2 < NST) { load(s + 2); cpwait<2>(); }
        else if (s + 1 < NST) { cpwait<1>(); }
        else { cpwait<0>(); }
        __syncthreads();

        const float* A = sm + (s % 3) * PSTG;
        const float* B = A + PA;
        #pragma unroll
        for (int ks = 0; ks < 4; ks++) {
            int kb = ks * 8;
            float a[2][4];
            #pragma unroll
            for (int mt = 0; mt < 2; mt++) {
                int r = wm + mt * 16;
                a[mt][0] = A[(kb + tig)     * 136 + r + g];
                a[mt][1] = A[(kb + tig)     * 136 + r + g + 8];
                a[mt][2] = A[(kb + tig + 4) * 136 + r + g];
                a[mt][3] = A[(kb + tig + 4) * 136 + r + g + 8];
            }
            #pragma unroll
            for (int nt = 0; nt < 4; nt++) {
                float b0 = B[(kb + tig)     * 72 + wn + nt * 8 + g];
                float b1 = B[(kb + tig + 4) * 72 + wn + nt * 8 + g];
                #pragma unroll
                for (int mt = 0; mt < 2; mt++)
                    mma_tf32(acc[mt][nt], a[mt][0], a[mt][1], a[mt][2], a[mt][3], b0, b1);
            }
        }
        __syncthreads();
    }

    #pragma unroll
    for (int mt = 0; mt < 2; mt++) {
        #pragma unroll
        for (int i = 0; i < 2; i++) {
            int r = r0 + wm + mt * 16 + g + i * 8;
            #pragma unroll
            for (int nt = 0; nt < 4; nt++) {
                int c = wn + nt * 8 + tig * 2;
                *(float2*)&D[r * DH + c] =
                    make_float2(acc[mt][nt][i * 2], acc[mt][nt][i * 2 + 1]);
            }
        }
    }
}

// =====================================================================
// Kernel 3: fused attention — identical arithmetic; AO stored tf32-converted.
// =====================================================================
#define AT_QS (64*68)
#define AT_KP (256*68)
#define AT_VP (256*72)
#define AT_PS (64*260)
#define AT_SMEM ((AT_QS + AT_KP + AT_VP + AT_PS + 256 + 64)*4)

__global__ __launch_bounds__(256) void attn_kernel()
{
    extern __shared__ float sm[];
    float* Qs   = sm;
    float* kps  = Qs + AT_QS;
    float* vps  = kps + AT_KP;
    float* Ps   = vps + AT_VP;
    float* redM = Ps + AT_PS;
    float* redS = redM + 128;

    const int bh = blockIdx.y;
    const float* kp = g_KP + bh * RP * DH;
    const float* vp = g_VP + bh * RP * DH;

    const int tid = threadIdx.x;
    const int wid = tid >> 5, lane = tid & 31, g = lane >> 2, tig = lane & 3;
    const int wm = (wid >> 1) * 16, wn = wid & 1;

    #pragma unroll
    for (int l = 0; l < 16; l++) {
        int idx = l * 256 + tid;
        int r = idx >> 4, c = (idx & 15) * 4;
        *(float4*)&kps[r * 68 + c] = cvt4(*(const float4*)&kp[r * DH + c]);
        *(float4*)&vps[r * 72 + c] = cvt4(*(const float4*)&vp[r * DH + c]);
    }

    const int b = bh >> 3, h = bh & 7;
    const float scale = 0.125f;

    for (int ci = 0; ci < 4; ci++) {
        const int n0 = blockIdx.x * 256 + ci * 64;
        const float* Qg = g_Q + (bh * NSEQ + n0) * DH;

        __syncthreads();
        #pragma unroll
        for (int l = 0; l < 4; l++) {
            int idx = l * 256 + tid;
            int r = idx >> 4, c = (idx & 15) * 4;
            *(float4*)&Qs[r * 68 + c] = cvt4(*(const float4*)&Qg[r * DH + c]);
        }
        __syncthreads();

        float acc[16][4] = {};
        #pragma unroll
        for (int ks = 0; ks < 8; ks++) {
            int kb = ks * 8;
            float a0 = Qs[(wm + g)     * 68 + kb + tig];
            float a1 = Qs[(wm + g + 8) * 68 + kb + tig];
            float a2 = Qs[(wm + g)     * 68 + kb + tig + 4];
            float a3 = Qs[(wm + g + 8) * 68 + kb + tig + 4];
            #pragma unroll
            for (int nt = 0; nt < 16; nt++) {
                int rr = wn * 128 + nt * 8 + g;
                float b0 = kps[rr * 68 + kb + tig];
                float b1 = kps[rr * 68 + kb + tig + 4];
                mma_tf32(acc[nt], a0, a1, a2, a3, b0, b1);
            }
        }

        const int r0 = wm + g, r1 = r0 + 8;
        float mx0 = -1e30f, mx1 = -1e30f;
        #pragma unroll
        for (int nt = 0; nt < 16; nt++) {
            mx0 = fmaxf(mx0, fmaxf(acc[nt][0], acc[nt][1]));
            mx1 = fmaxf(mx1, fmaxf(acc[nt][2], acc[nt][3]));
        }
        mx0 = fmaxf(mx0, __shfl_xor_sync(0xffffffffu, mx0, 1));
        mx0 = fmaxf(mx0, __shfl_xor_sync(0xffffffffu, mx0, 2));
        mx1 = fmaxf(mx1, __shfl_xor_sync(0xffffffffu, mx1, 1));
        mx1 = fmaxf(mx1, __shfl_xor_sync(0xffffffffu, mx1, 2));
        if (tig == 0) { redM[r0 * 2 + wn] = mx0; redM[r1 * 2 + wn] = mx1; }
        __syncthreads();
        mx0 = fmaxf(redM[r0 * 2], redM[r0 * 2 + 1]) * scale;
        mx1 = fmaxf(redM[r1 * 2], redM[r1 * 2 + 1]) * scale;

        float s0 = 0.f, s1 = 0.f;
        #pragma unroll
        for (int nt = 0; nt < 16; nt++) {
            int c = wn * 128 + nt * 8 + tig * 2;
            float e0 = __expf(acc[nt][0] * scale - mx0);
            float e1 = __expf(acc[nt][1] * scale - mx0);
            s0 += e0 + e1;
            *(float2*)&Ps[r0 * 260 + c] = make_float2(f2tf(e0), f2tf(e1));
            float e2 = __expf(acc[nt][2] * scale - mx1);
            float e3 = __expf(acc[nt][3] * scale - mx1);
            s1 += e2 + e3;
            *(float2*)&Ps[r1 * 260 + c] = make_float2(f2tf(e2), f2tf(e3));
        }
        s0 += __shfl_xor_sync(0xffffffffu, s0, 1);
        s0 += __shfl_xor_sync(0xffffffffu, s0, 2);
        s1 += __shfl_xor_sync(0xffffffffu, s1, 1);
        s1 += __shfl_xor_sync(0xffffffffu, s1, 2);
        if (tig == 0) { redS[r0 * 2 + wn] = s0; redS[r1 * 2 + wn] = s1; }
        __syncthreads();

        float acc2[4][4] = {};
        #pragma unroll 8
        for (int ks = 0; ks < 32; ks++) {
            int kb = ks * 8;
            float a0 = Ps[(wm + g)     * 260 + kb + tig];
            float a1 = Ps[(wm + g + 8) * 260 + kb + tig];
            float a2 = Ps[(wm + g)     * 260 + kb + tig + 4];
            float a3 = Ps[(wm + g + 8) * 260 + kb + tig + 4];
            #pragma unroll
            for (int nt = 0; nt < 4; nt++) {
                int cc = wn * 32 + nt * 8 + g;
                float b0 = vps[(kb + tig)     * 72 + cc];
                float b1 = vps[(kb + tig + 4) * 72 + cc];
                mma_tf32(acc2[nt], a0, a1, a2, a3, b0, b1);
            }
        }

        const float inv0 = __frcp_rn(redS[r0 * 2] + redS[r0 * 2 + 1]);
        const float inv1 = __frcp_rn(redS[r1 * 2] + redS[r1 * 2 + 1]);
        float* ao = g_AO + (long)(b * NSEQ + n0) * DM + h * DH;
        #pragma unroll
        for (int nt = 0; nt < 4; nt++) {
            int c = wn * 32 + nt * 8 + tig * 2;
            *(float2*)&ao[r0 * DM + c] =
                make_float2(f2tf(acc2[nt][0] * inv0), f2tf(acc2[nt][1] * inv0));
            *(float2*)&ao[r1 * DM + c] =
                make_float2(f2tf(acc2[nt][2] * inv1), f2tf(acc2[nt][3] * inv1));
        }
    }
}

// =====================================================================
// Kernel 4: out = AO @ w_out + b_out.  Pure LDS+HMMA inner loop.
// =====================================================================
__global__ __launch_bounds__(256, 2) void outproj_kernel(
    const float* __restrict__ bo, float* __restrict__ out)
{
    extern __shared__ float sm[];

    const int m0 = blockIdx.y * 128, n0 = blockIdx.x * 128;
    const int tid = threadIdx.x;
    const int wid = tid >> 5, lane = tid & 31, g = lane >> 2, tig = lane & 3;
    const int wm = (wid >> 1) * 32, wn = (wid & 1) * 64;

    const int arow = tid >> 3, acol = (tid & 7) * 4;
    const int brow = tid >> 5, bcol = (tid & 31) * 4;

    const float* wo = g_wc + 3 * DM * DM;
    float acc[2][8][4] = {};

    auto load = [&](int s) {
        float* buf = sm + (s % 3) * QSTG;
        const int k0 = s * 32;
        const uint32_t ab = s2u(buf), bb = s2u(buf + QA);
        #pragma unroll
        for (int l = 0; l < 4; l++) {
            int r = l * 32 + arow;
            cpa16(ab + (r * 36 + acol) * 4, &g_AO[(m0 + r) * DM + k0 + acol]);
        }
        #pragma unroll
        for (int l = 0; l < 4; l++) {
            int r = l * 8 + brow;
            cpa16(bb + (r * 136 + bcol) * 4, &wo[(k0 + r) * DM + n0 + bcol]);
        }
        cpcommit();
    };

    load(0); load(1);
    for (int s = 0; s < 16; s++) {
        if (s + 2 < 16) { load(s + 2); cpwait<2>(); }
        else if (s + 1 < 16) { cpwait<1>(); }
        else { cpwait<0>(); }
        __syncthreads();

        const float* A = sm + (s % 3) * QSTG;
        const float* B = A + QA;
        #pragma unroll
        for (int ks = 0; ks < 4; ks++) {
            int kb = ks * 8;
            float a[2][4];
            #pragma unroll
            for (int mt = 0; mt < 2; mt++) {
                int r = wm + mt * 16;
                a[mt][0] = A[(r + g)     * 36 + kb + tig];
                a[mt][1] = A[(r + g + 8) * 36 + kb + tig];
                a[mt][2] = A[(r + g)     * 36 + kb + tig + 4];
                a[mt][3] = A[(r + g + 8) * 36 + kb + tig + 4];
            }
            #pragma unroll
            for (int nt = 0; nt < 8; nt++) {
                float b0 = B[(kb + tig)     * 136 + wn + nt * 8 + g];
                float b1 = B[(kb + tig + 4) * 136 + wn + nt * 8 + g];
                #pragma unroll
                for (int mt = 0; mt < 2; mt++)
                    mma_tf32(acc[mt][nt], a[mt][0], a[mt][1], a[mt][2], a[mt][3], b0, b1);
            }
        }
        __syncthreads();
    }

    #pragma unroll
    for (int mt = 0; mt < 2; mt++) {
        #pragma unroll
        for (int i = 0; i < 2; i++) {
            int m = m0 + wm + mt * 16 + g + i * 8;
            #pragma unroll
            for (int nt = 0; nt < 8; nt++) {
                int c = n0 + wn + nt * 8 + tig * 2;
                float2 bias = *(const float2*)&bo[c];
                *(float2*)&out[m * DM + c] =
                    make_float2(acc[mt][nt][i * 2] + bias.x, acc[mt][nt][i * 2 + 1] + bias.y);
            }
        }
    }
}

// =====================================================================
extern "C" void kernel_launch(void* const* d_in, const int* in_sizes, int n_in,
                              void* d_out, int out_size)
{
    (void)in_sizes; (void)n_in; (void)out_size;
    const float* x  = (const float*)d_in[0];
    const float* wq = (const float*)d_in[1];
    const float* wk = (const float*)d_in[2];
    const float* wv = (const float*)d_in[3];
    const float* E  = (const float*)d_in[4];
    const float* F  = (const float*)d_in[5];
    const float* wo = (const float*)d_in[6];
    const float* bo = (const float*)d_in[7];
    float* out = (float*)d_out;

    cudaFuncSetAttribute(qkv_kernel,     cudaFuncAttributeMaxDynamicSharedMemorySize, QKV_SMEM);
    cudaFuncSetAttribute(proj_kernel,    cudaFuncAttributeMaxDynamicSharedMemorySize, PRJ_SMEM);
    cudaFuncSetAttribute(attn_kernel,    cudaFuncAttributeMaxDynamicSharedMemorySize, AT_SMEM);
    cudaFuncSetAttribute(outproj_kernel, cudaFuncAttributeMaxDynamicSharedMemorySize, QKV_SMEM);

    float *p_xc, *p_wc, *p_Ec, *p_Fc;
    cudaGetSymbolAddress((void**)&p_xc, g_xc);
    cudaGetSymbolAddress((void**)&p_wc, g_wc);
    cudaGetSymbolAddress((void**)&p_Ec, g_Ec);
    cudaGetSymbolAddress((void**)&p_Fc, g_Fc);

    // marshal: pre-convert all GEMM operands to tf32 values
    cvtk<<<MTOT*DM/1024, 256>>>(x, p_xc, MTOT*DM);
    cvtk<<<DM*DM/1024, 256>>>(wq, p_wc,            DM*DM);
    cvtk<<<DM*DM/1024, 256>>>(wk, p_wc + DM*DM,    DM*DM);
    cvtk<<<DM*DM/1024, 256>>>(wv, p_wc + 2*DM*DM,  DM*DM);
    cvtk<<<DM*DM/1024, 256>>>(wo, p_wc + 3*DM*DM,  DM*DM);
    cvtk<<<HEADS*NSEQ*RP/1024, 256>>>(E, p_Ec, HEADS*NSEQ*RP);
    cvtk<<<HEADS*NSEQ*RP/1024, 256>>>(F, p_Fc, HEADS*NSEQ*RP);

    qkv_kernel    <<<dim3(4, 256, 3), 256, QKV_SMEM>>>();
    proj_kernel   <<<dim3(2, 64, 2),  256, PRJ_SMEM>>>();
    attn_kernel   <<<dim3(16, 64),    256, AT_SMEM>>>();
    outproj_kernel<<<dim3(4, 256),    256, QKV_SMEM>>>(bo, out);
}